// round 14
// baseline (speedup 1.0000x reference)
#include <cuda_runtime.h>
#include <cstdint>

// GCMConv on 8x8x16x16 lattice — fused tensor-core (tf32) pipeline, v2.
//   B[(w*9+e)*NS + site] float2 (re,im), tf32-truncated  -> GEMM cols = 2*site+ri
//   C[80 rows][9 e][16 cols] = [W1;W2;pad] @ B   (mma m16n8k8 tf32, A-frags in regs)
//   combine in smem: M_uv[e][col] = C1[e][col] + sign(col) * C2[eT][col]
//   apply (column-mapped): w_out[u] = (M_u8+c3I) + sum_c w_c@(M_uc+c3I) + w_c^dag@(M_u4c+c3I)

#define NS 16384

__device__ float2 g_B[16 * 9 * NS];   // [(w*9+e)*NS + site]

__device__ __forceinline__ uint32_t tf32_bits(float x) {
    uint32_t u;
    asm("cvt.rna.tf32.f32 %0, %1;" : "=r"(u) : "f"(x));
    return u;
}

// ---------------------------------------------------------------------------
__global__ __launch_bounds__(256) void transport_kernel(const float* __restrict__ x) {
    int g = blockIdx.x * 256 + threadIdx.x;   // 0 .. 4*NS-1
    int site = g & (NS - 1);
    int a = g >> 14;                           // axis 0..3

    int d3 = site & 15, d2 = (site >> 4) & 15, d1 = (site >> 8) & 7, d0 = (site >> 11) & 7;
    int nbr;
    if (a == 0)      nbr = site + ((((d0 + 1) & 7) - d0) << 11);
    else if (a == 1) nbr = site + ((((d1 + 1) & 7) - d1) << 8);
    else if (a == 2) nbr = site + ((((d2 + 1) & 15) - d2) << 4);
    else             nbr = site + (((d3 + 1) & 15) - d3);

    float Ur[3][3], Ui[3][3];
    {
        const float2* up = (const float2*)(x + site * 144 + a * 18);
#pragma unroll
        for (int m = 0; m < 9; m++) {
            float2 t = up[m];
            Ur[m / 3][m % 3] = t.x;
            Ui[m / 3][m % 3] = t.y;
        }
    }

#pragma unroll
    for (int c = 0; c < 4; c++) {
        float Wr[3][3], Wi[3][3];
        const float2* wp = (const float2*)(x + nbr * 144 + (4 + c) * 18);
#pragma unroll
        for (int m = 0; m < 9; m++) {
            float2 t = wp[m];
            Wr[m / 3][m % 3] = t.x;
            Wi[m / 3][m % 3] = t.y;
        }
        float t1r[3][3], t1i[3][3];
#pragma unroll
        for (int i = 0; i < 3; i++)
#pragma unroll
            for (int kk = 0; kk < 3; kk++) {
                float cr = 0.f, ci = 0.f;
#pragma unroll
                for (int j = 0; j < 3; j++) {
                    cr += Ur[i][j] * Wr[j][kk] - Ui[i][j] * Wi[j][kk];
                    ci += Ur[i][j] * Wi[j][kk] + Ui[i][j] * Wr[j][kk];
                }
                t1r[i][kk] = cr;
                t1i[i][kk] = ci;
            }
        int w = a * 4 + c;
#pragma unroll
        for (int i = 0; i < 3; i++)
#pragma unroll
            for (int kk = 0; kk < 3; kk++) {
                float cr = 0.f, ci = 0.f;
#pragma unroll
                for (int j = 0; j < 3; j++) {
                    float br = Ur[kk][j], bi = -Ui[kk][j];
                    cr += t1r[i][j] * br - t1i[i][j] * bi;
                    ci += t1r[i][j] * bi + t1i[i][j] * br;
                }
                g_B[(w * 9 + i * 3 + kk) * NS + site] =
                    make_float2(__uint_as_float(tf32_bits(cr)), __uint_as_float(tf32_bits(ci)));
            }
    }
}

// ---------------------------------------------------------------------------
// Fused GEMM + combine + apply. Block = 8 sites, 128 threads (4 warps).
#define CS_STR 171                      // Cs row stride (floats), odd vs 32 banks
#define E_STR  19                       // element-plane stride inside a Cs row
#define WS_OFF (80 * CS_STR)
#define BS_OFF (WS_OFF + 80 * 17)
#define XS_OFF (BS_OFF + 16 * 152)
#define C3_OFF (XS_OFF + 8 * 146)
#define SMEM_FLOATS (C3_OFF + 36)

__global__ __launch_bounds__(128) void fused_kernel(const float* __restrict__ x,
                                                    const float* __restrict__ weight,
                                                    float* __restrict__ out) {
    extern __shared__ float sm[];
    float* Cs = sm;
    float* Ws = sm + WS_OFF;
    float* Bs = sm + BS_OFF;
    float* xs = sm + XS_OFF;
    float* c3s = sm + C3_OFF;

    const int tid = threadIdx.x;
    const int siteBase = blockIdx.x * 8;
    const int lane = tid & 31, warp = tid >> 5;
    const int lg = lane >> 2, lt = lane & 3;

    // ---- stage Ws (tf32 weights, rows 0-35 = W1, 36-71 = W2, 72-79 = 0) ----
    for (int s = tid; s < 80 * 16; s += 128) {
        int row = s >> 4, k = s & 15;
        float val = 0.f;
        if (row < 36)      val = weight[(row / 9) * 297 + (row % 9) * 33 + k];
        else if (row < 72) { int r = row - 36; val = weight[(r / 9) * 297 + (r % 9) * 33 + 16 + k]; }
        Ws[row * 17 + k] = __uint_as_float(tf32_bits(val));
    }
    if (tid < 36) c3s[tid] = weight[(tid / 9) * 297 + (tid % 9) * 33 + 32];

    // ---- stage Bs: [k][plane*16 + col], col = 2*(site-siteBase)+ri ----
    {
        const float4* b4 = reinterpret_cast<const float4*>(g_B);
        for (int i4 = tid; i4 < 576; i4 += 128) {
            int row = i4 >> 2, q = i4 & 3;           // row = w*9+plane
            float4 v = b4[((row * NS + siteBase) >> 1) + q];
            float* d = Bs + (row / 9) * 152 + (row % 9) * 16 + q * 4;
            d[0] = v.x; d[1] = v.y; d[2] = v.z; d[3] = v.w;
        }
    }

    // ---- stage xs: 8 sites x 144 floats (stride 146) ----
    {
        const float4* x4 = reinterpret_cast<const float4*>(x + siteBase * 144);
        for (int i4 = tid; i4 < 288; i4 += 128) {
            float4 v = x4[i4];
            int flat = i4 * 4;
            int s = flat / 144, c = flat % 144;
            float* d = xs + s * 146 + c;
            d[0] = v.x; d[1] = v.y; d[2] = v.z; d[3] = v.w;
        }
    }
    __syncthreads();

    // ---- copy gauge links (channels 0-3) to out ----
    for (int i = tid; i < 576; i += 128) {
        int s = i / 72, c = i % 72;
        out[(siteBase + s) * 144 + c] = xs[s * 146 + c];
    }

    // ---- load A fragments ONCE into registers (shared by all n-tiles) ----
    uint32_t af[5][2][4];
#pragma unroll
    for (int mt = 0; mt < 5; mt++)
#pragma unroll
        for (int ks = 0; ks < 2; ks++) {
            af[mt][ks][0] = __float_as_uint(Ws[(mt * 16 + lg) * 17 + ks * 8 + lt]);
            af[mt][ks][1] = __float_as_uint(Ws[(mt * 16 + lg + 8) * 17 + ks * 8 + lt]);
            af[mt][ks][2] = __float_as_uint(Ws[(mt * 16 + lg) * 17 + ks * 8 + lt + 4]);
            af[mt][ks][3] = __float_as_uint(Ws[(mt * 16 + lg + 8) * 17 + ks * 8 + lt + 4]);
        }

    // ---- mma: 18 n-tiles (9 planes x 2 col-halves) over 4 warps ----
    for (int t = warp; t < 18; t += 4) {
        int p = t >> 1, nh = t & 1;
        float d[5][4];
#pragma unroll
        for (int mt = 0; mt < 5; mt++)
#pragma unroll
            for (int q = 0; q < 4; q++) d[mt][q] = 0.f;

#pragma unroll
        for (int ks = 0; ks < 2; ks++) {
            uint32_t b0 = __float_as_uint(Bs[(ks * 8 + lt) * 152 + p * 16 + nh * 8 + lg]);
            uint32_t b1 = __float_as_uint(Bs[(ks * 8 + lt + 4) * 152 + p * 16 + nh * 8 + lg]);
#pragma unroll
            for (int mt = 0; mt < 5; mt++) {
                asm volatile(
                    "mma.sync.aligned.m16n8k8.row.col.f32.tf32.tf32.f32 "
                    "{%0,%1,%2,%3},{%4,%5,%6,%7},{%8,%9},{%0,%1,%2,%3};"
                    : "+f"(d[mt][0]), "+f"(d[mt][1]), "+f"(d[mt][2]), "+f"(d[mt][3])
                    : "r"(af[mt][ks][0]), "r"(af[mt][ks][1]),
                      "r"(af[mt][ks][2]), "r"(af[mt][ks][3]), "r"(b0), "r"(b1));
            }
        }
        int cb = p * E_STR + nh * 8 + 2 * lt;
#pragma unroll
        for (int mt = 0; mt < 5; mt++) {
            Cs[(mt * 16 + lg) * CS_STR + cb]         = d[mt][0];
            Cs[(mt * 16 + lg) * CS_STR + cb + 1]     = d[mt][1];
            Cs[(mt * 16 + lg + 8) * CS_STR + cb]     = d[mt][2];
            Cs[(mt * 16 + lg + 8) * CS_STR + cb + 1] = d[mt][3];
        }
    }
    __syncthreads();

    // ---- combine: M_uv[e][col] = C1 + sign(col)*C2[eT][col], in place over C1 ----
    for (int n = tid; n < 36 * 144; n += 128) {
        int uv = n / 144, rem = n % 144;
        int e = rem >> 4, col = rem & 15;
        int eT = (e % 3) * 3 + e / 3;
        float sign = (col & 1) ? -1.f : 1.f;
        float val = Cs[uv * CS_STR + e * E_STR + col]
                  + sign * Cs[(36 + uv) * CS_STR + eT * E_STR + col];
        Cs[uv * CS_STR + e * E_STR + col] = val;
    }
    __syncthreads();

    // ---- apply: thread = (site s, u, output column kk); 96 active threads ----
    if (tid < 96) {
        const int s = tid & 7;
        const int r = tid >> 3;        // 0..11
        const int u = r / 3;
        const int kk = r % 3;
        const int c0 = 2 * s;

        float ar[3], ai[3];
        // v = 8 (A = I)
        {
            const float* m8 = Cs + (u * 9 + 8) * CS_STR;
            float c3 = c3s[u * 9 + 8];
#pragma unroll
            for (int i = 0; i < 3; i++) {
                ar[i] = m8[(i * 3 + kk) * E_STR + c0] + ((i == kk) ? c3 : 0.f);
                ai[i] = m8[(i * 3 + kk) * E_STR + c0 + 1];
            }
        }

#pragma unroll
        for (int v = 0; v < 4; v++) {
            const float* mv = Cs + (u * 9 + v) * CS_STR;
            const float* nv = Cs + (u * 9 + 4 + v) * CS_STR;
            const float c3a = c3s[u * 9 + v];
            const float c3b = c3s[u * 9 + 4 + v];
            const float* wv = xs + s * 146 + (4 + v) * 18;
#pragma unroll
            for (int j = 0; j < 3; j++) {
                const int em = j * 3 + kk;
                float mr = mv[em * E_STR + c0];
                float mi = mv[em * E_STR + c0 + 1];
                float nr = nv[em * E_STR + c0];
                float ni = nv[em * E_STR + c0 + 1];
                if (j == kk) { mr += c3a; nr += c3b; }
#pragma unroll
                for (int i = 0; i < 3; i++) {
                    float wr = wv[(i * 3 + j) * 2], wi = wv[(i * 3 + j) * 2 + 1];
                    ar[i] += wr * mr - wi * mi;
                    ai[i] += wr * mi + wi * mr;
                    float vr = wv[(j * 3 + i) * 2], vi = wv[(j * 3 + i) * 2 + 1];
                    ar[i] += vr * nr + vi * ni;
                    ai[i] += vr * ni - vi * nr;
                }
            }
        }

        float2* dst = (float2*)(out + (siteBase + s) * 144 + (4 + u) * 18);
#pragma unroll
        for (int i = 0; i < 3; i++)
            dst[i * 3 + kk] = make_float2(ar[i], ai[i]);
    }
}

// ---------------------------------------------------------------------------
extern "C" void kernel_launch(void* const* d_in, const int* in_sizes, int n_in,
                              void* d_out, int out_size) {
    const float* x = (const float*)d_in[0];
    const float* weight = (const float*)d_in[1];
    float* out = (float*)d_out;

    static_assert(SMEM_FLOATS * 4 < 100 * 1024, "smem");
    cudaFuncSetAttribute(fused_kernel, cudaFuncAttributeMaxDynamicSharedMemorySize,
                         SMEM_FLOATS * 4);

    transport_kernel<<<4 * NS / 256, 256>>>(x);
    fused_kernel<<<NS / 8, 128, SMEM_FLOATS * 4>>>(x, weight, out);
}

// round 15
// speedup vs baseline: 2.2231x; 2.2231x over previous
#include <cuda_runtime.h>

// GCMConv on 8x8x16x16 lattice — single fused kernel, T staged in shared memory.
// Block = 32 sites x 128 threads. Phase 1 (warp=axis a, lane=site): transport
//   T_{a,c} = U_a(x) w_c(x+a) U_a(x)^dag  -> smem (computed once per block,
//   shared by all 4 output channels). Phase 2 (warp=u, lane=site): M-form
//   contract, 3 passes of 3 v, T streamed from smem (LDS, 29-cyc latency,
//   no prefetch ring needed -> small live set, no spills).
//   M_v = sum_k c1_{vk} T_k + c2_{vk} T_k^dag (+ c3_v I)
//   w_out[u] = M_8 + sum_c w_c @ M_c + w_c^dag @ M_{4+c}

#define NS 16384

__global__ __launch_bounds__(128, 3) void gcm_kernel(const float* __restrict__ x,
                                                     const float* __restrict__ weight,
                                                     float* __restrict__ out) {
    __shared__ float2 Ts[16 * 9 * 32];   // [(k*9+m)*32 + lane] transported matrices
    __shared__ float2 Wcs[4 * 9 * 32];   // [(c*9+m)*32 + lane] own-site fields
    __shared__ float  wt[4 * 297];       // [u*297 + w*9 + v] transposed weights

    const int tid = threadIdx.x;
    const int lane = tid & 31;           // site within block
    const int wrp = tid >> 5;            // a (phase 1) / u (phase 2)
    const int siteBase = blockIdx.x * 32;
    const int site = siteBase + lane;

    // ---- stage weights (transposed per u) ----
    for (int s = tid; s < 4 * 297; s += 128) {
        int u = s / 297, rem = s % 297;
        int v = rem / 33, w = rem % 33;
        wt[u * 297 + w * 9 + v] = weight[u * 297 + rem];
    }

    // ---- coalesced U-copy: channels 0..3 (first 72 floats of each site) ----
    {
        const float4* x4 = reinterpret_cast<const float4*>(x);
        float4* o4 = reinterpret_cast<float4*>(out);
        for (int f = tid; f < 32 * 18; f += 128) {
            int s = f / 18, c4 = f % 18;
            o4[(siteBase + s) * 36 + c4] = x4[(siteBase + s) * 36 + c4];
        }
    }

    // ================= Phase 1: transport (warp = axis a) =================
    {
        const int a = wrp;
        // periodic +1 neighbor; dims (8,8,16,16), strides (2048,256,16,1)
        int d3 = site & 15, d2 = (site >> 4) & 15, d1 = (site >> 8) & 7, d0 = (site >> 11) & 7;
        int nbr;
        if (a == 0)      nbr = site + ((((d0 + 1) & 7) - d0) << 11);
        else if (a == 1) nbr = site + ((((d1 + 1) & 7) - d1) << 8);
        else if (a == 2) nbr = site + ((((d2 + 1) & 15) - d2) << 4);
        else             nbr = site + (((d3 + 1) & 15) - d3);

        float Ur[3][3], Ui[3][3];
        {
            const float2* up = (const float2*)(x + site * 144 + a * 18);
#pragma unroll
            for (int m = 0; m < 9; m++) {
                float2 t = up[m];
                Ur[m / 3][m % 3] = t.x;
                Ui[m / 3][m % 3] = t.y;
            }
        }

#pragma unroll
        for (int c = 0; c < 4; c++) {
            float Wr[3][3], Wi[3][3];
            const float2* wp = (const float2*)(x + nbr * 144 + (4 + c) * 18);
#pragma unroll
            for (int m = 0; m < 9; m++) {
                float2 t = wp[m];
                Wr[m / 3][m % 3] = t.x;
                Wi[m / 3][m % 3] = t.y;
            }
            // t1 = U @ W
            float t1r[3][3], t1i[3][3];
#pragma unroll
            for (int i = 0; i < 3; i++)
#pragma unroll
                for (int kk = 0; kk < 3; kk++) {
                    float cr = 0.f, ci = 0.f;
#pragma unroll
                    for (int j = 0; j < 3; j++) {
                        cr += Ur[i][j] * Wr[j][kk] - Ui[i][j] * Wi[j][kk];
                        ci += Ur[i][j] * Wi[j][kk] + Ui[i][j] * Wr[j][kk];
                    }
                    t1r[i][kk] = cr;
                    t1i[i][kk] = ci;
                }
            // T = t1 @ U^dag -> smem
            int r = a * 4 + c;
#pragma unroll
            for (int i = 0; i < 3; i++)
#pragma unroll
                for (int kk = 0; kk < 3; kk++) {
                    float cr = 0.f, ci = 0.f;
#pragma unroll
                    for (int j = 0; j < 3; j++) {
                        float br = Ur[kk][j], bi = -Ui[kk][j];
                        cr += t1r[i][j] * br - t1i[i][j] * bi;
                        ci += t1r[i][j] * bi + t1i[i][j] * br;
                    }
                    Ts[(r * 9 + i * 3 + kk) * 32 + lane] = make_float2(cr, ci);
                }
        }

        // own-site field copy: channel c = a
        {
            const float2* wp = (const float2*)(x + site * 144 + (4 + a) * 18);
#pragma unroll
            for (int m = 0; m < 9; m++)
                Wcs[(a * 9 + m) * 32 + lane] = wp[m];
        }
    }
    __syncthreads();

    // ================= Phase 2: contract (warp = u) =================
    const int u = wrp;
    const float* wtu = wt + u * 297;

    float accr[3][3], acci[3][3];
#pragma unroll
    for (int i = 0; i < 3; i++)
#pragma unroll
        for (int j = 0; j < 3; j++) { accr[i][j] = 0.f; acci[i][j] = 0.f; }

    // 3 passes over v-groups {0,1,2}, {3,4,5}, {6,7,8}
#pragma unroll
    for (int vb = 0; vb < 9; vb += 3) {
        float Mr[3][9], Mi[3][9];
#pragma unroll
        for (int t = 0; t < 3; t++)
#pragma unroll
            for (int m = 0; m < 9; m++) { Mr[t][m] = 0.f; Mi[t][m] = 0.f; }

#pragma unroll 2
        for (int k = 0; k < 16; k++) {
            float2 T[9];
#pragma unroll
            for (int m = 0; m < 9; m++)
                T[m] = Ts[(k * 9 + m) * 32 + lane];

#pragma unroll
            for (int t = 0; t < 3; t++) {
                const int v = vb + t;
                float c1 = wtu[k * 9 + v];
                float c2 = wtu[(16 + k) * 9 + v];
#pragma unroll
                for (int i = 0; i < 3; i++)
#pragma unroll
                    for (int j = 0; j < 3; j++) {
                        Mr[t][i * 3 + j] += c1 * T[i * 3 + j].x + c2 * T[j * 3 + i].x;
                        Mi[t][i * 3 + j] += c1 * T[i * 3 + j].y - c2 * T[j * 3 + i].y;
                    }
            }
        }

        // epilogue: N = M + c3 I ; acc += A_v @ N
#pragma unroll
        for (int t = 0; t < 3; t++) {
            const int v = vb + t;
            float c3 = wtu[288 + v];
            float nr[3][3], ni[3][3];
#pragma unroll
            for (int i = 0; i < 3; i++)
#pragma unroll
                for (int j = 0; j < 3; j++) {
                    nr[i][j] = Mr[t][i * 3 + j] + ((i == j) ? c3 : 0.f);
                    ni[i][j] = Mi[t][i * 3 + j];
                }

            if (v == 8) {
#pragma unroll
                for (int i = 0; i < 3; i++)
#pragma unroll
                    for (int j = 0; j < 3; j++) { accr[i][j] += nr[i][j]; acci[i][j] += ni[i][j]; }
            } else {
                const int c = (v < 4) ? v : (v - 4);
                float wr[3][3], wi[3][3];
#pragma unroll
                for (int m = 0; m < 9; m++) {
                    float2 t2 = Wcs[(c * 9 + m) * 32 + lane];
                    wr[m / 3][m % 3] = t2.x;
                    wi[m / 3][m % 3] = t2.y;
                }
                if (v < 4) {
                    // acc += w_c @ N
#pragma unroll
                    for (int i = 0; i < 3; i++)
#pragma unroll
                        for (int kk = 0; kk < 3; kk++) {
                            float cr = accr[i][kk], ci = acci[i][kk];
#pragma unroll
                            for (int j = 0; j < 3; j++) {
                                cr += wr[i][j] * nr[j][kk] - wi[i][j] * ni[j][kk];
                                ci += wr[i][j] * ni[j][kk] + wi[i][j] * nr[j][kk];
                            }
                            accr[i][kk] = cr; acci[i][kk] = ci;
                        }
                } else {
                    // acc += w_c^dag @ N : conj(w[j][i]) * N[j][kk]
#pragma unroll
                    for (int i = 0; i < 3; i++)
#pragma unroll
                        for (int kk = 0; kk < 3; kk++) {
                            float cr = accr[i][kk], ci = acci[i][kk];
#pragma unroll
                            for (int j = 0; j < 3; j++) {
                                cr += wr[j][i] * nr[j][kk] + wi[j][i] * ni[j][kk];
                                ci += wr[j][i] * ni[j][kk] - wi[j][i] * nr[j][kk];
                            }
                            accr[i][kk] = cr; acci[i][kk] = ci;
                        }
                }
            }
        }
    }

    float2* dst = (float2*)(out + site * 144 + (4 + u) * 18);
#pragma unroll
    for (int i = 0; i < 3; i++)
#pragma unroll
        for (int j = 0; j < 3; j++)
            dst[i * 3 + j] = make_float2(accr[i][j], acci[i][j]);
}

extern "C" void kernel_launch(void* const* d_in, const int* in_sizes, int n_in,
                              void* d_out, int out_size) {
    const float* x = (const float*)d_in[0];
    const float* weight = (const float*)d_in[1];
    float* out = (float*)d_out;

    gcm_kernel<<<NS / 32, 128>>>(x, weight, out);
}